// round 9
// baseline (speedup 1.0000x reference)
#include <cuda_runtime.h>
#include <math.h>
#include <stdint.h>

#define B_DIM 4096
#define IN_DIM 1024
#define H_DIM 2048
#define A_DIM 64
#define A2_DIM 4096

// ---------------- scratch (__device__ globals; no allocs allowed) ----------
__device__ float g_inc [B_DIM * IN_DIM];        // tf32-rounded inputs
__device__ float g_hinc[B_DIM * H_DIM];         // tf32-rounded hidden
__device__ float g_W1c [H_DIM * IN_DIM];
__device__ float g_Wihc[3 * H_DIM * H_DIM];
__device__ float g_Whhc[3 * H_DIM * H_DIM];
__device__ float g_W2c [A2_DIM * H_DIM];
__device__ float g_x  [B_DIM * H_DIM];          // fc1 out (relu, tf32-rounded)
__device__ float g_gi [B_DIM * 3 * H_DIM];
__device__ float g_gh [B_DIM * 3 * H_DIM];
__device__ float g_hc [B_DIM * H_DIM];          // tf32-rounded new hidden
__device__ float g_q  [B_DIM * A2_DIM];

// ---------------- helpers --------------------------------------------------
__device__ __forceinline__ uint32_t smem_u32(const void* p) {
    uint32_t a;
    asm("{ .reg .u64 t; cvta.to.shared.u64 t, %1; cvt.u32.u64 %0, t; }"
        : "=r"(a) : "l"(p));
    return a;
}
__device__ __forceinline__ float to_tf32(float x) {
    float r;
    asm("cvt.rna.tf32.f32 %0, %1;" : "=f"(r) : "f"(x));
    return r;
}
__device__ __forceinline__ void cp_async4(uint32_t dst, const void* src) {
    asm volatile("cp.async.ca.shared.global [%0], [%1], 4;" :: "r"(dst), "l"(src));
}
__device__ __forceinline__ void mma_tf32(float* c,
                                         uint32_t a0, uint32_t a1, uint32_t a2, uint32_t a3,
                                         uint32_t b0, uint32_t b1) {
    asm volatile(
        "mma.sync.aligned.m16n8k8.row.col.f32.tf32.tf32.f32 "
        "{%0,%1,%2,%3}, {%4,%5,%6,%7}, {%8,%9}, {%0,%1,%2,%3};"
        : "+f"(c[0]), "+f"(c[1]), "+f"(c[2]), "+f"(c[3])
        : "r"(a0), "r"(a1), "r"(a2), "r"(a3), "r"(b0), "r"(b1));
}

// ---------------- tf32 mma.sync GEMM ---------------------------------------
// C[M,N] = A[M,K] @ Bw[N,K]^T + bias.  CTA tile 256(M) x 128(N), BK=32,
// 512 threads (16 warps = 8(M) x 2(N), warp tile 32x64).
// Smem k-permuted: element k stored at column (k&3)*8 + (k>>2), so each
// thread's mma fragment k-set {t, t+4, t+8, ...} is contiguous -> LDS.128
// feeds two k-steps.  Operands are pre-rounded to tf32 (no cvt in hot loop).
#define BMT 256
#define BNT 128
#define BK 32
#define ROWF 36                           // 32 floats + 4 pad
#define NROWS (BMT + BNT)                 // 384 rows per stage
#define STAGE_F (NROWS * ROWF)            // floats per stage
#define SMEM_BYTES (2 * STAGE_F * 4)      // 110592 B double-buffered

template<int MODE>   // 0: bias only, 1: bias + relu + tf32-round output
__global__ __launch_bounds__(512, 1)
void gemm_tf32(const float* __restrict__ A, const float* __restrict__ Bw,
               const float* __restrict__ bias, float* __restrict__ C,
               int K, int N) {
    extern __shared__ float sm[];
    const int tid  = threadIdx.x;
    const int bm   = blockIdx.y * BMT;
    const int bn   = blockIdx.x * BNT;
    const int warp = tid >> 5, lane = tid & 31;
    const int wm   = (warp & 7) * 32;
    const int wn   = (warp >> 3) * 64;
    const int g    = lane >> 2;           // row-in-8 group
    const int t    = lane & 3;            // k phase
    const int NC   = K >> 5;

    const uint32_t sb = smem_u32(sm);
    // permuted store position for this lane's k within a 32-chunk
    const int spos = (lane & 3) * 8 + (lane >> 2);

    float acc[2][8][4];
    #pragma unroll
    for (int mt = 0; mt < 2; mt++)
        #pragma unroll
        for (int nt = 0; nt < 8; nt++)
            #pragma unroll
            for (int i = 0; i < 4; i++) acc[mt][nt][i] = 0.0f;

    const float* Ap = A  + (size_t)bm * K;
    const float* Bp = Bw + (size_t)bn * K;

    // loader: one warp covers one row per op (32 consecutive k, scattered
    // into permuted smem columns). Coalesced gmem, conflict-free smem.
    auto load_stage = [&](int stage, int k0) {
        const uint32_t base = sb + stage * (STAGE_F * 4);
        #pragma unroll
        for (int i = 0; i < 16; i++) {     // A: 256 rows, 16 per warp
            const int row = warp + i * 16;
            cp_async4(base + (uint32_t)(row * ROWF + spos) * 4,
                      Ap + (size_t)row * K + k0 + lane);
        }
        #pragma unroll
        for (int i = 0; i < 8; i++) {      // B: 128 rows, 8 per warp
            const int row = warp + i * 16;
            cp_async4(base + (uint32_t)((BMT + row) * ROWF + spos) * 4,
                      Bp + (size_t)row * K + k0 + lane);
        }
    };

    load_stage(0, 0);
    asm volatile("cp.async.commit_group;" ::: "memory");
    if (NC > 1) load_stage(1, BK);
    asm volatile("cp.async.commit_group;" ::: "memory");

    for (int c = 0; c < NC; c++) {
        asm volatile("cp.async.wait_group 1;" ::: "memory");
        __syncthreads();

        const float* sA = sm + (c & 1) * STAGE_F;
        const float* sB = sA + BMT * ROWF;

        #pragma unroll
        for (int kh = 0; kh < 2; kh++) {   // each kh = two k-steps (k8 x2)
            uint4 af[2][2];                // [mt][row g / g+8]
            #pragma unroll
            for (int mt = 0; mt < 2; mt++) {
                const float* pa = sA + (wm + mt * 16 + g) * ROWF + t * 8 + kh * 4;
                af[mt][0] = *reinterpret_cast<const uint4*>(pa);
                af[mt][1] = *reinterpret_cast<const uint4*>(pa + 8 * ROWF);
            }
            uint4 bf[8];
            #pragma unroll
            for (int nt = 0; nt < 8; nt++)
                bf[nt] = *reinterpret_cast<const uint4*>(
                    sB + (wn + nt * 8 + g) * ROWF + t * 8 + kh * 4);

            #pragma unroll
            for (int mt = 0; mt < 2; mt++)
                #pragma unroll
                for (int nt = 0; nt < 8; nt++) {
                    // ks = 2*kh  : fragment components (.x = k t, .y = k t+4)
                    mma_tf32(acc[mt][nt],
                             af[mt][0].x, af[mt][1].x, af[mt][0].y, af[mt][1].y,
                             bf[nt].x, bf[nt].y);
                    // ks = 2*kh+1: components (.z, .w)
                    mma_tf32(acc[mt][nt],
                             af[mt][0].z, af[mt][1].z, af[mt][0].w, af[mt][1].w,
                             bf[nt].z, bf[nt].w);
                }
        }

        __syncthreads();
        if (c + 2 < NC) load_stage(c & 1, (c + 2) << 5);
        asm volatile("cp.async.commit_group;" ::: "memory");
    }

    // epilogue: bias (+relu +tf32-round), float2 stores
    #pragma unroll
    for (int mt = 0; mt < 2; mt++) {
        const int r0 = bm + wm + mt * 16 + g;
        #pragma unroll
        for (int nt = 0; nt < 8; nt++) {
            const int cc = bn + wn + nt * 8 + 2 * t;
            const float2 bv = *reinterpret_cast<const float2*>(bias + cc);
            float2 v0, v1;
            v0.x = acc[mt][nt][0] + bv.x;
            v0.y = acc[mt][nt][1] + bv.y;
            v1.x = acc[mt][nt][2] + bv.x;
            v1.y = acc[mt][nt][3] + bv.y;
            if (MODE == 1) {
                v0.x = to_tf32(fmaxf(v0.x, 0.0f));
                v0.y = to_tf32(fmaxf(v0.y, 0.0f));
                v1.x = to_tf32(fmaxf(v1.x, 0.0f));
                v1.y = to_tf32(fmaxf(v1.y, 0.0f));
            }
            *reinterpret_cast<float2*>(C + (size_t)r0 * N + cc)       = v0;
            *reinterpret_cast<float2*>(C + (size_t)(r0 + 8) * N + cc) = v1;
        }
    }
}

// ---------------- elementwise kernels --------------------------------------
__global__ void cvt_kernel(const float4* __restrict__ s, float4* __restrict__ d, int n4) {
    int i = blockIdx.x * 256 + threadIdx.x;
    if (i < n4) {
        float4 v = s[i];
        v.x = to_tf32(v.x); v.y = to_tf32(v.y); v.z = to_tf32(v.z); v.w = to_tf32(v.w);
        d[i] = v;
    }
}

__global__ void gru_kernel(const float4* __restrict__ hin,
                           float4* __restrict__ hout,
                           float4* __restrict__ hc) {
    const int idx = blockIdx.x * 256 + threadIdx.x;      // over B*H/4
    const int b = idx >> 9;                              // H/4 = 512
    const int i = idx & 511;
    const float4* gi = reinterpret_cast<const float4*>(g_gi) + (size_t)b * (3 * H_DIM / 4);
    const float4* gh = reinterpret_cast<const float4*>(g_gh) + (size_t)b * (3 * H_DIM / 4);
    const float4 ir = gi[i], iz = gi[512 + i], inn = gi[1024 + i];
    const float4 hr = gh[i], hz = gh[512 + i], hn  = gh[1024 + i];
    const float4 h0 = hin[idx];
    float4 o, oc;
    {
        float r = 1.0f / (1.0f + expf(-(ir.x + hr.x)));
        float z = 1.0f / (1.0f + expf(-(iz.x + hz.x)));
        float n = tanhf(inn.x + r * hn.x);
        o.x = (1.0f - z) * n + z * h0.x; oc.x = to_tf32(o.x);
    }
    {
        float r = 1.0f / (1.0f + expf(-(ir.y + hr.y)));
        float z = 1.0f / (1.0f + expf(-(iz.y + hz.y)));
        float n = tanhf(inn.y + r * hn.y);
        o.y = (1.0f - z) * n + z * h0.y; oc.y = to_tf32(o.y);
    }
    {
        float r = 1.0f / (1.0f + expf(-(ir.z + hr.z)));
        float z = 1.0f / (1.0f + expf(-(iz.z + hz.z)));
        float n = tanhf(inn.z + r * hn.z);
        o.z = (1.0f - z) * n + z * h0.z; oc.z = to_tf32(o.z);
    }
    {
        float r = 1.0f / (1.0f + expf(-(ir.w + hr.w)));
        float z = 1.0f / (1.0f + expf(-(iz.w + hz.w)));
        float n = tanhf(inn.w + r * hn.w);
        o.w = (1.0f - z) * n + z * h0.w; oc.w = to_tf32(o.w);
    }
    hout[idx] = o;
    hc[idx] = oc;
}

__global__ void decode_kernel(float* __restrict__ out) {
    __shared__ float s[A2_DIM];
    const int b = blockIdx.x;
    const float* qr = g_q + (size_t)b * A2_DIM;
    for (int i = threadIdx.x; i < A2_DIM; i += 256) s[i] = qr[i];
    __syncthreads();
    const int t = threadIdx.x;
    if (t < A_DIM) {
        float m = -3.402823466e38f;
        #pragma unroll 8
        for (int k = 0; k < A_DIM; k++) m = fmaxf(m, s[t + k]);
        out[(size_t)(2 * b) * A_DIM + t] = m;
    } else if (t < 2 * A_DIM) {
        const int j = t - A_DIM;
        float m = -3.402823466e38f;
        #pragma unroll 8
        for (int k = 0; k < A_DIM; k++)
            m = fmaxf(m, s[(j + A_DIM * k + (A2_DIM - 1)) & (A2_DIM - 1)]);
        out[(size_t)(2 * b + 1) * A_DIM + j] = m;
    }
}

// ---------------- launch ----------------------------------------------------
extern "C" void kernel_launch(void* const* d_in, const int* in_sizes, int n_in,
                              void* d_out, int out_size) {
    const float* inputs = (const float*)d_in[0];
    const float* hidden = (const float*)d_in[1];
    const float* W1  = (const float*)d_in[2];
    const float* b1  = (const float*)d_in[3];
    const float* Wih = (const float*)d_in[4];
    const float* Whh = (const float*)d_in[5];
    const float* bih = (const float*)d_in[6];
    const float* bhh = (const float*)d_in[7];
    const float* W2  = (const float*)d_in[8];
    const float* b2  = (const float*)d_in[9];
    float* out = (float*)d_out;
    float* hout = out + (size_t)2 * B_DIM * A_DIM;   // h region of output

    void *pinc, *phinc, *pW1c, *pWihc, *pWhhc, *pW2c, *px, *pgi, *pgh, *phc, *pq;
    cudaGetSymbolAddress(&pinc,  g_inc);
    cudaGetSymbolAddress(&phinc, g_hinc);
    cudaGetSymbolAddress(&pW1c,  g_W1c);
    cudaGetSymbolAddress(&pWihc, g_Wihc);
    cudaGetSymbolAddress(&pWhhc, g_Whhc);
    cudaGetSymbolAddress(&pW2c,  g_W2c);
    cudaGetSymbolAddress(&px,    g_x);
    cudaGetSymbolAddress(&pgi,   g_gi);
    cudaGetSymbolAddress(&pgh,   g_gh);
    cudaGetSymbolAddress(&phc,   g_hc);
    cudaGetSymbolAddress(&pq,    g_q);

    cudaFuncSetAttribute(gemm_tf32<0>, cudaFuncAttributeMaxDynamicSharedMemorySize, SMEM_BYTES);
    cudaFuncSetAttribute(gemm_tf32<1>, cudaFuncAttributeMaxDynamicSharedMemorySize, SMEM_BYTES);

    // one-shot RNA tf32 pre-rounding of raw GEMM operands
    auto cvt = [](const void* s, void* d, size_t n) {
        cvt_kernel<<<(unsigned)((n / 4 + 255) / 256), 256>>>(
            (const float4*)s, (float4*)d, (int)(n / 4));
    };
    cvt(inputs, pinc,  (size_t)B_DIM * IN_DIM);
    cvt(hidden, phinc, (size_t)B_DIM * H_DIM);
    cvt(W1,  pW1c,  (size_t)H_DIM * IN_DIM);
    cvt(Wih, pWihc, (size_t)3 * H_DIM * H_DIM);
    cvt(Whh, pWhhc, (size_t)3 * H_DIM * H_DIM);
    cvt(W2,  pW2c,  (size_t)A2_DIM * H_DIM);

    const dim3 blk(512);

    // fc1 + relu (+round): x = relu(inputs @ W1^T + b1)
    gemm_tf32<1><<<dim3(H_DIM / BNT, B_DIM / BMT), blk, SMEM_BYTES>>>(
        (const float*)pinc, (const float*)pW1c, b1, (float*)px, IN_DIM, H_DIM);

    // gi = x @ Wih^T + bih ; gh = h_in @ Whh^T + bhh
    gemm_tf32<0><<<dim3(3 * H_DIM / BNT, B_DIM / BMT), blk, SMEM_BYTES>>>(
        (const float*)px, (const float*)pWihc, bih, (float*)pgi, H_DIM, 3 * H_DIM);
    gemm_tf32<0><<<dim3(3 * H_DIM / BNT, B_DIM / BMT), blk, SMEM_BYTES>>>(
        (const float*)phinc, (const float*)pWhhc, bhh, (float*)pgh, H_DIM, 3 * H_DIM);

    // GRU elementwise -> exact h into d_out, rounded h into scratch
    gru_kernel<<<(B_DIM * H_DIM / 4) / 256, 256>>>(
        (const float4*)hidden, (float4*)hout, (float4*)phc);

    // fc2: q = h @ W2^T + b2
    gemm_tf32<0><<<dim3(A2_DIM / BNT, B_DIM / BMT), blk, SMEM_BYTES>>>(
        (const float*)phc, (const float*)pW2c, b2, (float*)pq, H_DIM, A2_DIM);

    // decode -> d_out[0 .. 2B*A)
    decode_kernel<<<B_DIM, 256>>>(out);
}

// round 10
// speedup vs baseline: 1.4568x; 1.4568x over previous
#include <cuda_runtime.h>
#include <math.h>
#include <stdint.h>

#define B_DIM 4096
#define IN_DIM 1024
#define H_DIM 2048
#define A_DIM 64
#define A2_DIM 4096

// ---------------- scratch (__device__ globals; no allocs allowed) ----------
// All GEMM operands live pre-rounded (tf32/RNA) AND k-permuted:
// within each 32-float K block, element k is stored at (k&3)*8 + (k>>2).
__device__ float g_inc [B_DIM * IN_DIM];
__device__ float g_hinc[B_DIM * H_DIM];
__device__ float g_W1c [H_DIM * IN_DIM];
__device__ float g_Wihc[3 * H_DIM * H_DIM];
__device__ float g_Whhc[3 * H_DIM * H_DIM];
__device__ float g_W2c [A2_DIM * H_DIM];
__device__ float g_x  [B_DIM * H_DIM];          // fc1 out (relu+round+perm)
__device__ float g_gi [B_DIM * 3 * H_DIM];      // plain layout
__device__ float g_gh [B_DIM * 3 * H_DIM];      // plain layout
__device__ float g_hc [B_DIM * H_DIM];          // new hidden (round+perm)
__device__ float g_q  [B_DIM * A2_DIM];         // plain layout

// ---------------- helpers --------------------------------------------------
__device__ __forceinline__ uint32_t smem_u32(const void* p) {
    uint32_t a;
    asm("{ .reg .u64 t; cvta.to.shared.u64 t, %1; cvt.u32.u64 %0, t; }"
        : "=r"(a) : "l"(p));
    return a;
}
__device__ __forceinline__ float to_tf32(float x) {
    float r;
    asm("cvt.rna.tf32.f32 %0, %1;" : "=f"(r) : "f"(x));
    return r;
}
__device__ __forceinline__ void cp_async16(uint32_t dst, const void* src) {
    asm volatile("cp.async.cg.shared.global [%0], [%1], 16;" :: "r"(dst), "l"(src));
}
__device__ __forceinline__ void mma_tf32(float* c,
                                         uint32_t a0, uint32_t a1, uint32_t a2, uint32_t a3,
                                         uint32_t b0, uint32_t b1) {
    asm volatile(
        "mma.sync.aligned.m16n8k8.row.col.f32.tf32.tf32.f32 "
        "{%0,%1,%2,%3}, {%4,%5,%6,%7}, {%8,%9}, {%0,%1,%2,%3};"
        : "+f"(c[0]), "+f"(c[1]), "+f"(c[2]), "+f"(c[3])
        : "r"(a0), "r"(a1), "r"(a2), "r"(a3), "r"(b0), "r"(b1));
}
// permuted position of column c within its row (32-block permutation)
__device__ __forceinline__ int kperm(int c) {
    return (c & ~31) + (c & 3) * 8 + ((c >> 2) & 7);
}

// ---------------- tf32 mma.sync GEMM ---------------------------------------
// C[M,N] = A[M,K] @ Bw[N,K]^T + bias. CTA 128x128, BK=32, 256 thr, occ 2,
// 3-stage cp.async pipeline. Operands pre-rounded + k-permuted in gmem, so
// cp.async copies verbatim and fragment reads are contiguous LDS.128.
#define BK 32
#define ROWF 36                           // 32 floats + 4 pad
#define TILE_F (128 * ROWF)
#define STAGE_F (2 * TILE_F)              // A + B
#define NSTG 3
#define SMEM_BYTES (NSTG * STAGE_F * 4)   // 110592 B

template<int MODE>   // 0: plain store; 1: relu + tf32-round + PERMUTED store
__global__ __launch_bounds__(256, 2)
void gemm_tf32(const float* __restrict__ A, const float* __restrict__ Bw,
               const float* __restrict__ bias, float* __restrict__ C,
               int K, int N) {
    extern __shared__ float sm[];
    const int tid  = threadIdx.x;
    const int bm   = blockIdx.y * 128;
    const int bn   = blockIdx.x * 128;
    const int warp = tid >> 5, lane = tid & 31;
    const int wm   = (warp & 3) * 32;
    const int wn   = (warp >> 2) * 64;
    const int g    = lane >> 2;           // row-in-8 group
    const int t    = lane & 3;            // k phase
    const int NC   = K >> 5;

    const uint32_t sb = smem_u32(sm);
    const int lrow = tid >> 3;            // loader: row 0..31 (+p*32)
    const int lcol = (tid & 7) * 4;       // 16B chunk within 32-block

    float acc[2][8][4];
    #pragma unroll
    for (int mt = 0; mt < 2; mt++)
        #pragma unroll
        for (int nt = 0; nt < 8; nt++)
            #pragma unroll
            for (int i = 0; i < 4; i++) acc[mt][nt][i] = 0.0f;

    const float* Ap = A  + (size_t)bm * K;
    const float* Bp = Bw + (size_t)bn * K;

    auto load_stage = [&](int stage, int k0) {
        const uint32_t ab = sb + stage * (STAGE_F * 4);
        const uint32_t bb = ab + TILE_F * 4;
        #pragma unroll
        for (int p = 0; p < 4; p++) {
            const int row = lrow + p * 32;
            cp_async16(ab + (uint32_t)(row * ROWF + lcol) * 4,
                       Ap + (size_t)row * K + k0 + lcol);
            cp_async16(bb + (uint32_t)(row * ROWF + lcol) * 4,
                       Bp + (size_t)row * K + k0 + lcol);
        }
    };

    load_stage(0, 0);
    asm volatile("cp.async.commit_group;" ::: "memory");
    load_stage(1, BK);
    asm volatile("cp.async.commit_group;" ::: "memory");

    int buf = 0;
    for (int c = 0; c < NC; c++) {
        asm volatile("cp.async.wait_group 1;" ::: "memory");
        __syncthreads();

        const float* sA = sm + buf * STAGE_F;
        const float* sB = sA + TILE_F;

        #pragma unroll
        for (int kh = 0; kh < 2; kh++) {   // each kh feeds two k8 steps
            uint4 af[2][2];
            #pragma unroll
            for (int mt = 0; mt < 2; mt++) {
                const float* pa = sA + (wm + mt * 16 + g) * ROWF + t * 8 + kh * 4;
                af[mt][0] = *reinterpret_cast<const uint4*>(pa);
                af[mt][1] = *reinterpret_cast<const uint4*>(pa + 8 * ROWF);
            }
            uint4 bf[8];
            #pragma unroll
            for (int nt = 0; nt < 8; nt++)
                bf[nt] = *reinterpret_cast<const uint4*>(
                    sB + (wn + nt * 8 + g) * ROWF + t * 8 + kh * 4);

            #pragma unroll
            for (int mt = 0; mt < 2; mt++)
                #pragma unroll
                for (int nt = 0; nt < 8; nt++) {
                    mma_tf32(acc[mt][nt],
                             af[mt][0].x, af[mt][1].x, af[mt][0].y, af[mt][1].y,
                             bf[nt].x, bf[nt].y);
                    mma_tf32(acc[mt][nt],
                             af[mt][0].z, af[mt][1].z, af[mt][0].w, af[mt][1].w,
                             bf[nt].z, bf[nt].w);
                }
        }

        __syncthreads();
        if (c + 2 < NC) {
            load_stage((buf + 2) % NSTG, (c + 2) << 5);
        }
        asm volatile("cp.async.commit_group;" ::: "memory");
        buf = (buf + 1) % NSTG;
    }

    // epilogue
    #pragma unroll
    for (int mt = 0; mt < 2; mt++) {
        const int r0 = bm + wm + mt * 16 + g;
        #pragma unroll
        for (int nt = 0; nt < 8; nt++) {
            const int cc = bn + wn + nt * 8 + 2 * t;
            const float2 bv = *reinterpret_cast<const float2*>(bias + cc);
            float v00 = acc[mt][nt][0] + bv.x;
            float v01 = acc[mt][nt][1] + bv.y;
            float v10 = acc[mt][nt][2] + bv.x;
            float v11 = acc[mt][nt][3] + bv.y;
            if (MODE == 1) {
                // relu + round + permuted scalar stores (feeds next GEMM as A)
                v00 = to_tf32(fmaxf(v00, 0.0f));
                v01 = to_tf32(fmaxf(v01, 0.0f));
                v10 = to_tf32(fmaxf(v10, 0.0f));
                v11 = to_tf32(fmaxf(v11, 0.0f));
                const int p0 = kperm(cc), p1 = kperm(cc + 1);
                C[(size_t)r0 * N + p0]       = v00;
                C[(size_t)r0 * N + p1]       = v01;
                C[(size_t)(r0 + 8) * N + p0] = v10;
                C[(size_t)(r0 + 8) * N + p1] = v11;
            } else {
                float2 v0 = make_float2(v00, v01);
                float2 v1 = make_float2(v10, v11);
                *reinterpret_cast<float2*>(C + (size_t)r0 * N + cc)       = v0;
                *reinterpret_cast<float2*>(C + (size_t)(r0 + 8) * N + cc) = v1;
            }
        }
    }
}

// ---------------- elementwise kernels --------------------------------------
// fused tf32-round + k-permute: out[f*4 + i] = tf32(in[block + inv(p)])
__global__ void cvt_perm_kernel(const float* __restrict__ in,
                                float* __restrict__ outp, int n4) {
    int f = blockIdx.x * 256 + threadIdx.x;
    if (f >= n4) return;
    const int p0 = (f * 4) & 31;
    const int base = f * 4 - p0;
    float4 v;
    {
        int pw = p0 + 0; v.x = to_tf32(in[base + (pw & 7) * 4 + (pw >> 3)]);
        pw = p0 + 1;     v.y = to_tf32(in[base + (pw & 7) * 4 + (pw >> 3)]);
        pw = p0 + 2;     v.z = to_tf32(in[base + (pw & 7) * 4 + (pw >> 3)]);
        pw = p0 + 3;     v.w = to_tf32(in[base + (pw & 7) * 4 + (pw >> 3)]);
    }
    *reinterpret_cast<float4*>(outp + f * 4) = v;
}

__global__ void gru_kernel(const float4* __restrict__ hin,
                           float4* __restrict__ hout,
                           float* __restrict__ hc) {
    const int idx = blockIdx.x * 256 + threadIdx.x;      // over B*H/4
    const int b = idx >> 9;                              // H/4 = 512
    const int i = idx & 511;
    const float4* gi = reinterpret_cast<const float4*>(g_gi) + (size_t)b * (3 * H_DIM / 4);
    const float4* gh = reinterpret_cast<const float4*>(g_gh) + (size_t)b * (3 * H_DIM / 4);
    const float4 ir = gi[i], iz = gi[512 + i], inn = gi[1024 + i];
    const float4 hr = gh[i], hz = gh[512 + i], hn  = gh[1024 + i];
    const float4 h0 = hin[idx];
    float4 o;
    float oc[4];
    {
        float r = 1.0f / (1.0f + expf(-(ir.x + hr.x)));
        float z = 1.0f / (1.0f + expf(-(iz.x + hz.x)));
        float n = tanhf(inn.x + r * hn.x);
        o.x = (1.0f - z) * n + z * h0.x; oc[0] = to_tf32(o.x);
    }
    {
        float r = 1.0f / (1.0f + expf(-(ir.y + hr.y)));
        float z = 1.0f / (1.0f + expf(-(iz.y + hz.y)));
        float n = tanhf(inn.y + r * hn.y);
        o.y = (1.0f - z) * n + z * h0.y; oc[1] = to_tf32(o.y);
    }
    {
        float r = 1.0f / (1.0f + expf(-(ir.z + hr.z)));
        float z = 1.0f / (1.0f + expf(-(iz.z + hz.z)));
        float n = tanhf(inn.z + r * hn.z);
        o.z = (1.0f - z) * n + z * h0.z; oc[2] = to_tf32(o.z);
    }
    {
        float r = 1.0f / (1.0f + expf(-(ir.w + hr.w)));
        float z = 1.0f / (1.0f + expf(-(iz.w + hz.w)));
        float n = tanhf(inn.w + r * hn.w);
        o.w = (1.0f - z) * n + z * h0.w; oc[3] = to_tf32(o.w);
    }
    hout[idx] = o;
    // permuted scalar stores of the rounded hidden (fc2 A operand)
    const int f0 = idx * 4;
    const int pin = f0 & 31;               // 4-aligned within 32-block
    const int base = f0 - pin;
    const int s = pin >> 2;
    hc[base + s +  0] = oc[0];
    hc[base + s +  8] = oc[1];
    hc[base + s + 16] = oc[2];
    hc[base + s + 24] = oc[3];
}

__global__ void decode_kernel(float* __restrict__ out) {
    __shared__ float s[A2_DIM];
    const int b = blockIdx.x;
    const float* qr = g_q + (size_t)b * A2_DIM;
    for (int i = threadIdx.x; i < A2_DIM; i += 256) s[i] = qr[i];
    __syncthreads();
    const int t = threadIdx.x;
    if (t < A_DIM) {
        float m = -3.402823466e38f;
        #pragma unroll 8
        for (int k = 0; k < A_DIM; k++) m = fmaxf(m, s[t + k]);
        out[(size_t)(2 * b) * A_DIM + t] = m;
    } else if (t < 2 * A_DIM) {
        const int j = t - A_DIM;
        float m = -3.402823466e38f;
        #pragma unroll 8
        for (int k = 0; k < A_DIM; k++)
            m = fmaxf(m, s[(j + A_DIM * k + (A2_DIM - 1)) & (A2_DIM - 1)]);
        out[(size_t)(2 * b + 1) * A_DIM + j] = m;
    }
}

// ---------------- launch ----------------------------------------------------
extern "C" void kernel_launch(void* const* d_in, const int* in_sizes, int n_in,
                              void* d_out, int out_size) {
    const float* inputs = (const float*)d_in[0];
    const float* hidden = (const float*)d_in[1];
    const float* W1  = (const float*)d_in[2];
    const float* b1  = (const float*)d_in[3];
    const float* Wih = (const float*)d_in[4];
    const float* Whh = (const float*)d_in[5];
    const float* bih = (const float*)d_in[6];
    const float* bhh = (const float*)d_in[7];
    const float* W2  = (const float*)d_in[8];
    const float* b2  = (const float*)d_in[9];
    float* out = (float*)d_out;
    float* hout = out + (size_t)2 * B_DIM * A_DIM;   // h region of output

    void *pinc, *phinc, *pW1c, *pWihc, *pWhhc, *pW2c, *px, *pgi, *pgh, *phc, *pq;
    cudaGetSymbolAddress(&pinc,  g_inc);
    cudaGetSymbolAddress(&phinc, g_hinc);
    cudaGetSymbolAddress(&pW1c,  g_W1c);
    cudaGetSymbolAddress(&pWihc, g_Wihc);
    cudaGetSymbolAddress(&pWhhc, g_Whhc);
    cudaGetSymbolAddress(&pW2c,  g_W2c);
    cudaGetSymbolAddress(&px,    g_x);
    cudaGetSymbolAddress(&pgi,   g_gi);
    cudaGetSymbolAddress(&pgh,   g_gh);
    cudaGetSymbolAddress(&phc,   g_hc);
    cudaGetSymbolAddress(&pq,    g_q);

    cudaFuncSetAttribute(gemm_tf32<0>, cudaFuncAttributeMaxDynamicSharedMemorySize, SMEM_BYTES);
    cudaFuncSetAttribute(gemm_tf32<1>, cudaFuncAttributeMaxDynamicSharedMemorySize, SMEM_BYTES);

    // one-shot tf32 round + k-permute of raw GEMM operands
    auto cvtp = [](const void* s, void* d, size_t n) {
        cvt_perm_kernel<<<(unsigned)((n / 4 + 255) / 256), 256>>>(
            (const float*)s, (float*)d, (int)(n / 4));
    };
    cvtp(inputs, pinc,  (size_t)B_DIM * IN_DIM);
    cvtp(hidden, phinc, (size_t)B_DIM * H_DIM);
    cvtp(W1,  pW1c,  (size_t)H_DIM * IN_DIM);
    cvtp(Wih, pWihc, (size_t)3 * H_DIM * H_DIM);
    cvtp(Whh, pWhhc, (size_t)3 * H_DIM * H_DIM);
    cvtp(W2,  pW2c,  (size_t)A2_DIM * H_DIM);

    const dim3 blk(256);

    // fc1 + relu (+round+perm): x = relu(inputs @ W1^T + b1)
    gemm_tf32<1><<<dim3(H_DIM / 128, B_DIM / 128), blk, SMEM_BYTES>>>(
        (const float*)pinc, (const float*)pW1c, b1, (float*)px, IN_DIM, H_DIM);

    // gi = x @ Wih^T + bih ; gh = h_in @ Whh^T + bhh
    gemm_tf32<0><<<dim3(3 * H_DIM / 128, B_DIM / 128), blk, SMEM_BYTES>>>(
        (const float*)px, (const float*)pWihc, bih, (float*)pgi, H_DIM, 3 * H_DIM);
    gemm_tf32<0><<<dim3(3 * H_DIM / 128, B_DIM / 128), blk, SMEM_BYTES>>>(
        (const float*)phinc, (const float*)pWhhc, bhh, (float*)pgh, H_DIM, 3 * H_DIM);

    // GRU elementwise -> exact h into d_out, rounded+permuted h into scratch
    gru_kernel<<<(B_DIM * H_DIM / 4) / 256, 256>>>(
        (const float4*)hidden, (float4*)hout, (float*)phc);

    // fc2: q = h @ W2^T + b2
    gemm_tf32<0><<<dim3(A2_DIM / 128, B_DIM / 128), blk, SMEM_BYTES>>>(
        (const float*)phc, (const float*)pW2c, b2, (float*)pq, H_DIM, A2_DIM);

    // decode -> d_out[0 .. 2B*A)
    decode_kernel<<<B_DIM, 256>>>(out);
}

// round 11
// speedup vs baseline: 1.4655x; 1.0060x over previous
#include <cuda_runtime.h>
#include <math.h>
#include <stdint.h>

#define B_DIM 4096
#define IN_DIM 1024
#define H_DIM 2048
#define A_DIM 64
#define A2_DIM 4096

// ---------------- scratch (__device__ globals; no allocs allowed) ----------
// All GEMM operands live pre-rounded (tf32/RNA) AND k-permuted:
// within each 32-float K block, element k is stored at (k&3)*8 + (k>>2).
__device__ float g_inc [B_DIM * IN_DIM];
__device__ float g_hinc[B_DIM * H_DIM];
__device__ float g_W1c [H_DIM * IN_DIM];
__device__ float g_Wihc[3 * H_DIM * H_DIM];
__device__ float g_Whhc[3 * H_DIM * H_DIM];
__device__ float g_W2c [A2_DIM * H_DIM];
__device__ float g_x  [B_DIM * H_DIM];          // fc1 out (relu+round+perm)
__device__ float g_gi [B_DIM * 3 * H_DIM];      // plain layout
__device__ float g_gh [B_DIM * 3 * H_DIM];      // plain layout
__device__ float g_hc [B_DIM * H_DIM];          // new hidden (round+perm)
__device__ float g_q  [B_DIM * A2_DIM];         // plain layout

// ---------------- helpers --------------------------------------------------
__device__ __forceinline__ uint32_t smem_u32(const void* p) {
    uint32_t a;
    asm("{ .reg .u64 t; cvta.to.shared.u64 t, %1; cvt.u32.u64 %0, t; }"
        : "=r"(a) : "l"(p));
    return a;
}
__device__ __forceinline__ float to_tf32(float x) {
    float r;
    asm("cvt.rna.tf32.f32 %0, %1;" : "=f"(r) : "f"(x));
    return r;
}
__device__ __forceinline__ void cp_async16(uint32_t dst, const void* src) {
    asm volatile("cp.async.cg.shared.global [%0], [%1], 16;" :: "r"(dst), "l"(src));
}
__device__ __forceinline__ void mma_tf32(float* c,
                                         uint32_t a0, uint32_t a1, uint32_t a2, uint32_t a3,
                                         uint32_t b0, uint32_t b1) {
    asm volatile(
        "mma.sync.aligned.m16n8k8.row.col.f32.tf32.tf32.f32 "
        "{%0,%1,%2,%3}, {%4,%5,%6,%7}, {%8,%9}, {%0,%1,%2,%3};"
        : "+f"(c[0]), "+f"(c[1]), "+f"(c[2]), "+f"(c[3])
        : "r"(a0), "r"(a1), "r"(a2), "r"(a3), "r"(b0), "r"(b1));
}
// permuted position of column c within its row (32-block permutation)
__device__ __forceinline__ int kperm(int c) {
    return (c & ~31) + (c & 3) * 8 + ((c >> 2) & 7);
}

// ---------------- tf32 mma.sync GEMM ---------------------------------------
// C[M,N] = A[M,K] @ Bw[N,K]^T + bias. CTA 128x128, BK=32, 256 thr, occ 2,
// 3-stage cp.async ring, ONE barrier per chunk (load issued right after the
// sync: the load target stage's previous readers all passed this barrier).
#define BK 32
#define ROWF 36                           // 32 floats + 4 pad
#define TILE_F (128 * ROWF)
#define STAGE_F (2 * TILE_F)              // A + B
#define NSTG 3
#define SMEM_BYTES (NSTG * STAGE_F * 4)   // 110592 B

template<int MODE>   // 0: plain store; 1: relu + tf32-round + PERMUTED store
__global__ __launch_bounds__(256, 2)
void gemm_tf32(const float* __restrict__ A, const float* __restrict__ Bw,
               const float* __restrict__ bias, float* __restrict__ C,
               int K, int N) {
    extern __shared__ float sm[];
    const int tid  = threadIdx.x;
    const int bm   = blockIdx.y * 128;
    const int bn   = blockIdx.x * 128;
    const int warp = tid >> 5, lane = tid & 31;
    const int wm   = (warp & 3) * 32;
    const int wn   = (warp >> 2) * 64;
    const int g    = lane >> 2;           // row-in-8 group
    const int t    = lane & 3;            // k phase
    const int NC   = K >> 5;

    const uint32_t sb = smem_u32(sm);
    const int lrow = tid >> 3;            // loader: row 0..31 (+p*32)
    const int lcol = (tid & 7) * 4;       // 16B chunk within 32-block

    float acc[2][8][4];
    #pragma unroll
    for (int mt = 0; mt < 2; mt++)
        #pragma unroll
        for (int nt = 0; nt < 8; nt++)
            #pragma unroll
            for (int i = 0; i < 4; i++) acc[mt][nt][i] = 0.0f;

    const float* Ap = A  + (size_t)bm * K;
    const float* Bp = Bw + (size_t)bn * K;

    auto load_stage = [&](int stage, int k0) {
        const uint32_t ab = sb + stage * (STAGE_F * 4);
        const uint32_t bb = ab + TILE_F * 4;
        #pragma unroll
        for (int p = 0; p < 4; p++) {
            const int row = lrow + p * 32;
            cp_async16(ab + (uint32_t)(row * ROWF + lcol) * 4,
                       Ap + (size_t)row * K + k0 + lcol);
            cp_async16(bb + (uint32_t)(row * ROWF + lcol) * 4,
                       Bp + (size_t)row * K + k0 + lcol);
        }
    };

    load_stage(0, 0);
    asm volatile("cp.async.commit_group;" ::: "memory");
    load_stage(1, BK);
    asm volatile("cp.async.commit_group;" ::: "memory");

    int buf = 0;
    for (int c = 0; c < NC; c++) {
        asm volatile("cp.async.wait_group 1;" ::: "memory");
        __syncthreads();

        // issue next loads FIRST: target stage (buf+2)%3 was last read in
        // iteration c-1, and every warp passed the barrier above since then.
        if (c + 2 < NC) load_stage((buf + 2) % NSTG, (c + 2) << 5);
        asm volatile("cp.async.commit_group;" ::: "memory");

        const float* sA = sm + buf * STAGE_F;
        const float* sB = sA + TILE_F;

        #pragma unroll
        for (int kh = 0; kh < 2; kh++) {   // each kh feeds two k8 steps
            uint4 af[2][2];
            #pragma unroll
            for (int mt = 0; mt < 2; mt++) {
                const float* pa = sA + (wm + mt * 16 + g) * ROWF + t * 8 + kh * 4;
                af[mt][0] = *reinterpret_cast<const uint4*>(pa);
                af[mt][1] = *reinterpret_cast<const uint4*>(pa + 8 * ROWF);
            }
            uint4 bf[8];
            #pragma unroll
            for (int nt = 0; nt < 8; nt++)
                bf[nt] = *reinterpret_cast<const uint4*>(
                    sB + (wn + nt * 8 + g) * ROWF + t * 8 + kh * 4);

            #pragma unroll
            for (int mt = 0; mt < 2; mt++)
                #pragma unroll
                for (int nt = 0; nt < 8; nt++) {
                    mma_tf32(acc[mt][nt],
                             af[mt][0].x, af[mt][1].x, af[mt][0].y, af[mt][1].y,
                             bf[nt].x, bf[nt].y);
                    mma_tf32(acc[mt][nt],
                             af[mt][0].z, af[mt][1].z, af[mt][0].w, af[mt][1].w,
                             bf[nt].z, bf[nt].w);
                }
        }

        buf = (buf + 1) % NSTG;
    }

    // epilogue
    #pragma unroll
    for (int mt = 0; mt < 2; mt++) {
        const int r0 = bm + wm + mt * 16 + g;
        #pragma unroll
        for (int nt = 0; nt < 8; nt++) {
            const int cc = bn + wn + nt * 8 + 2 * t;
            const float2 bv = *reinterpret_cast<const float2*>(bias + cc);
            float v00 = acc[mt][nt][0] + bv.x;
            float v01 = acc[mt][nt][1] + bv.y;
            float v10 = acc[mt][nt][2] + bv.x;
            float v11 = acc[mt][nt][3] + bv.y;
            if (MODE == 1) {
                // relu + round + permuted scalar stores (feeds next GEMM as A)
                v00 = to_tf32(fmaxf(v00, 0.0f));
                v01 = to_tf32(fmaxf(v01, 0.0f));
                v10 = to_tf32(fmaxf(v10, 0.0f));
                v11 = to_tf32(fmaxf(v11, 0.0f));
                const int p0 = kperm(cc), p1 = kperm(cc + 1);
                C[(size_t)r0 * N + p0]       = v00;
                C[(size_t)r0 * N + p1]       = v01;
                C[(size_t)(r0 + 8) * N + p0] = v10;
                C[(size_t)(r0 + 8) * N + p1] = v11;
            } else {
                float2 v0 = make_float2(v00, v01);
                float2 v1 = make_float2(v10, v11);
                *reinterpret_cast<float2*>(C + (size_t)r0 * N + cc)       = v0;
                *reinterpret_cast<float2*>(C + (size_t)(r0 + 8) * N + cc) = v1;
            }
        }
    }
}

// ---------------- elementwise kernels --------------------------------------
// tf32-round + k-permute, one thread per 32-float block: float4 in AND out.
__global__ void cvt_perm_kernel(const float4* __restrict__ in,
                                float4* __restrict__ outp, int nblk) {
    const int b = blockIdx.x * 256 + threadIdx.x;
    if (b >= nblk) return;
    const float4* src = in + (size_t)b * 8;
    float v[32];
    #pragma unroll
    for (int q = 0; q < 8; q++) {
        float4 x = src[q];
        v[q * 4 + 0] = x.x; v[q * 4 + 1] = x.y;
        v[q * 4 + 2] = x.z; v[q * 4 + 3] = x.w;
    }
    float o[32];
    #pragma unroll
    for (int k = 0; k < 32; k++)
        o[(k & 3) * 8 + (k >> 2)] = to_tf32(v[k]);
    float4* dst = outp + (size_t)b * 8;
    #pragma unroll
    for (int q = 0; q < 8; q++)
        dst[q] = make_float4(o[q * 4 + 0], o[q * 4 + 1], o[q * 4 + 2], o[q * 4 + 3]);
}

__global__ void gru_kernel(const float4* __restrict__ hin,
                           float4* __restrict__ hout,
                           float* __restrict__ hc) {
    const int idx = blockIdx.x * 256 + threadIdx.x;      // over B*H/4
    const int b = idx >> 9;                              // H/4 = 512
    const int i = idx & 511;
    const float4* gi = reinterpret_cast<const float4*>(g_gi) + (size_t)b * (3 * H_DIM / 4);
    const float4* gh = reinterpret_cast<const float4*>(g_gh) + (size_t)b * (3 * H_DIM / 4);
    const float4 ir = gi[i], iz = gi[512 + i], inn = gi[1024 + i];
    const float4 hr = gh[i], hz = gh[512 + i], hn  = gh[1024 + i];
    const float4 h0 = hin[idx];
    float4 o;
    float oc[4];
    {
        float r = 1.0f / (1.0f + expf(-(ir.x + hr.x)));
        float z = 1.0f / (1.0f + expf(-(iz.x + hz.x)));
        float n = tanhf(inn.x + r * hn.x);
        o.x = (1.0f - z) * n + z * h0.x; oc[0] = to_tf32(o.x);
    }
    {
        float r = 1.0f / (1.0f + expf(-(ir.y + hr.y)));
        float z = 1.0f / (1.0f + expf(-(iz.y + hz.y)));
        float n = tanhf(inn.y + r * hn.y);
        o.y = (1.0f - z) * n + z * h0.y; oc[1] = to_tf32(o.y);
    }
    {
        float r = 1.0f / (1.0f + expf(-(ir.z + hr.z)));
        float z = 1.0f / (1.0f + expf(-(iz.z + hz.z)));
        float n = tanhf(inn.z + r * hn.z);
        o.z = (1.0f - z) * n + z * h0.z; oc[2] = to_tf32(o.z);
    }
    {
        float r = 1.0f / (1.0f + expf(-(ir.w + hr.w)));
        float z = 1.0f / (1.0f + expf(-(iz.w + hz.w)));
        float n = tanhf(inn.w + r * hn.w);
        o.w = (1.0f - z) * n + z * h0.w; oc[3] = to_tf32(o.w);
    }
    hout[idx] = o;
    // permuted scalar stores of the rounded hidden (fc2 A operand);
    // 8-lane groups write 32B-contiguous runs -> coalesced.
    const int f0 = idx * 4;
    const int pin = f0 & 31;               // 4-aligned within 32-block
    const int base = f0 - pin;
    const int s = pin >> 2;
    hc[base + s +  0] = oc[0];
    hc[base + s +  8] = oc[1];
    hc[base + s + 16] = oc[2];
    hc[base + s + 24] = oc[3];
}

__global__ void decode_kernel(float* __restrict__ out) {
    __shared__ float s[A2_DIM];
    const int b = blockIdx.x;
    const float* qr = g_q + (size_t)b * A2_DIM;
    for (int i = threadIdx.x; i < A2_DIM; i += 256) s[i] = qr[i];
    __syncthreads();
    const int t = threadIdx.x;
    if (t < A_DIM) {
        float m = -3.402823466e38f;
        #pragma unroll 8
        for (int k = 0; k < A_DIM; k++) m = fmaxf(m, s[t + k]);
        out[(size_t)(2 * b) * A_DIM + t] = m;
    } else if (t < 2 * A_DIM) {
        const int j = t - A_DIM;
        float m = -3.402823466e38f;
        #pragma unroll 8
        for (int k = 0; k < A_DIM; k++)
            m = fmaxf(m, s[(j + A_DIM * k + (A2_DIM - 1)) & (A2_DIM - 1)]);
        out[(size_t)(2 * b + 1) * A_DIM + j] = m;
    }
}

// ---------------- launch ----------------------------------------------------
extern "C" void kernel_launch(void* const* d_in, const int* in_sizes, int n_in,
                              void* d_out, int out_size) {
    const float* inputs = (const float*)d_in[0];
    const float* hidden = (const float*)d_in[1];
    const float* W1  = (const float*)d_in[2];
    const float* b1  = (const float*)d_in[3];
    const float* Wih = (const float*)d_in[4];
    const float* Whh = (const float*)d_in[5];
    const float* bih = (const float*)d_in[6];
    const float* bhh = (const float*)d_in[7];
    const float* W2  = (const float*)d_in[8];
    const float* b2  = (const float*)d_in[9];
    float* out = (float*)d_out;
    float* hout = out + (size_t)2 * B_DIM * A_DIM;   // h region of output

    void *pinc, *phinc, *pW1c, *pWihc, *pWhhc, *pW2c, *px, *pgi, *pgh, *phc, *pq;
    cudaGetSymbolAddress(&pinc,  g_inc);
    cudaGetSymbolAddress(&phinc, g_hinc);
    cudaGetSymbolAddress(&pW1c,  g_W1c);
    cudaGetSymbolAddress(&pWihc, g_Wihc);
    cudaGetSymbolAddress(&pWhhc, g_Whhc);
    cudaGetSymbolAddress(&pW2c,  g_W2c);
    cudaGetSymbolAddress(&px,    g_x);
    cudaGetSymbolAddress(&pgi,   g_gi);
    cudaGetSymbolAddress(&pgh,   g_gh);
    cudaGetSymbolAddress(&phc,   g_hc);
    cudaGetSymbolAddress(&pq,    g_q);

    cudaFuncSetAttribute(gemm_tf32<0>, cudaFuncAttributeMaxDynamicSharedMemorySize, SMEM_BYTES);
    cudaFuncSetAttribute(gemm_tf32<1>, cudaFuncAttributeMaxDynamicSharedMemorySize, SMEM_BYTES);

    // one-shot tf32 round + k-permute of raw GEMM operands (32-float blocks)
    auto cvtp = [](const void* s, void* d, size_t n) {
        const int nblk = (int)(n / 32);
        cvt_perm_kernel<<<(nblk + 255) / 256, 256>>>(
            (const float4*)s, (float4*)d, nblk);
    };
    cvtp(inputs, pinc,  (size_t)B_DIM * IN_DIM);
    cvtp(hidden, phinc, (size_t)B_DIM * H_DIM);
    cvtp(W1,  pW1c,  (size_t)H_DIM * IN_DIM);
    cvtp(Wih, pWihc, (size_t)3 * H_DIM * H_DIM);
    cvtp(Whh, pWhhc, (size_t)3 * H_DIM * H_DIM);
    cvtp(W2,  pW2c,  (size_t)A2_DIM * H_DIM);

    const dim3 blk(256);

    // fc1 + relu (+round+perm): x = relu(inputs @ W1^T + b1)
    gemm_tf32<1><<<dim3(H_DIM / 128, B_DIM / 128), blk, SMEM_BYTES>>>(
        (const float*)pinc, (const float*)pW1c, b1, (float*)px, IN_DIM, H_DIM);

    // gi = x @ Wih^T + bih ; gh = h_in @ Whh^T + bhh
    gemm_tf32<0><<<dim3(3 * H_DIM / 128, B_DIM / 128), blk, SMEM_BYTES>>>(
        (const float*)px, (const float*)pWihc, bih, (float*)pgi, H_DIM, 3 * H_DIM);
    gemm_tf32<0><<<dim3(3 * H_DIM / 128, B_DIM / 128), blk, SMEM_BYTES>>>(
        (const float*)phinc, (const float*)pWhhc, bhh, (float*)pgh, H_DIM, 3 * H_DIM);

    // GRU elementwise -> exact h into d_out, rounded+permuted h into scratch
    gru_kernel<<<(B_DIM * H_DIM / 4) / 256, 256>>>(
        (const float4*)hidden, (float4*)hout, (float*)phc);

    // fc2: q = h @ W2^T + b2
    gemm_tf32<0><<<dim3(A2_DIM / 128, B_DIM / 128), blk, SMEM_BYTES>>>(
        (const float*)phc, (const float*)pW2c, b2, (float*)pq, H_DIM, A2_DIM);

    // decode -> d_out[0 .. 2B*A)
    decode_kernel<<<B_DIM, 256>>>(out);
}

// round 12
// speedup vs baseline: 3.0414x; 2.0753x over previous
#include <cuda_runtime.h>
#include <cuda_fp16.h>
#include <math.h>
#include <stdint.h>

#define B_DIM 4096
#define IN_DIM 1024
#define H_DIM 2048
#define A_DIM 64
#define A2_DIM 4096

// ---------------- scratch (__device__ globals; no allocs allowed) ----------
// GEMM operands stored as fp16 pairs (uint32 = half2), k-PERMUTED:
// within each 32-k block, element k lives at pos = 8*((k&7)>>1) + 2*(k>>3) + (k&1).
// This makes each mma thread's m16n8k16 fragment set one contiguous 16B run.
__device__ uint32_t g_inc [B_DIM * IN_DIM / 2];
__device__ uint32_t g_hinc[B_DIM * H_DIM / 2];
__device__ uint32_t g_W1c [H_DIM * IN_DIM / 2];
__device__ uint32_t g_Wihc[3 * H_DIM * H_DIM / 2];
__device__ uint32_t g_Whhc[3 * H_DIM * H_DIM / 2];
__device__ uint32_t g_W2c [A2_DIM * H_DIM / 2];
__device__ uint32_t g_x   [B_DIM * H_DIM / 2];      // fc1 out (relu, fp16, perm)
__device__ float    g_gi  [B_DIM * 3 * H_DIM];      // fp32 plain
__device__ float    g_gh  [B_DIM * 3 * H_DIM];      // fp32 plain
__device__ uint32_t g_hc  [B_DIM * H_DIM / 2];      // new hidden (fp16, perm)
__device__ float    g_q   [B_DIM * A2_DIM];         // fp32 plain

// ---------------- helpers --------------------------------------------------
__device__ __forceinline__ uint32_t smem_u32(const void* p) {
    uint32_t a;
    asm("{ .reg .u64 t; cvta.to.shared.u64 t, %1; cvt.u32.u64 %0, t; }"
        : "=r"(a) : "l"(p));
    return a;
}
__device__ __forceinline__ uint32_t h2u(float a, float b) {
    __half2 h = __floats2half2_rn(a, b);     // low = a (even k), high = b
    return *reinterpret_cast<uint32_t*>(&h);
}
__device__ __forceinline__ void cp_async16(uint32_t dst, const void* src) {
    asm volatile("cp.async.cg.shared.global [%0], [%1], 16;" :: "r"(dst), "l"(src));
}
__device__ __forceinline__ void mma_f16(float* c,
                                        uint32_t a0, uint32_t a1, uint32_t a2, uint32_t a3,
                                        uint32_t b0, uint32_t b1) {
    asm volatile(
        "mma.sync.aligned.m16n8k16.row.col.f32.f16.f16.f32 "
        "{%0,%1,%2,%3}, {%4,%5,%6,%7}, {%8,%9}, {%0,%1,%2,%3};"
        : "+f"(c[0]), "+f"(c[1]), "+f"(c[2]), "+f"(c[3])
        : "r"(a0), "r"(a1), "r"(a2), "r"(a3), "r"(b0), "r"(b1));
}
// uint32 index (within a row of N/2 uint32) of the half2 holding (k, k+1), k even
__device__ __forceinline__ int hperm_u32(int k) {
    return (k >> 5) * 16 + ((k & 7) >> 1) * 4 + ((k & 31) >> 3);
}

// ---------------- fp16 mma.sync GEMM ---------------------------------------
// C[M,N] = A[M,K] @ Bw[N,K]^T + bias. CTA 128x128, BK=32, 256 thr, occ 2,
// 3-stage cp.async ring, one barrier per chunk. Operands fp16 permuted in
// gmem; each row-chunk is 64B; one LDS.128 = full K32 fragment for a thread.
#define ATILE_B 8192                      // 128 rows x 64 B
#define STAGE_B (2 * ATILE_B)             // A + B
#define NSTG 3
#define SMEM_BYTES (NSTG * STAGE_B)       // 49152 B

template<int MODE>   // 0: fp32 plain store; 1: relu + fp16 PERMUTED store
__global__ __launch_bounds__(256, 2)
void gemm_f16k(const uint32_t* __restrict__ A, const uint32_t* __restrict__ Bw,
               const float* __restrict__ bias, void* __restrict__ Cout,
               int K, int N) {
    extern __shared__ uint32_t sm[];
    const int tid  = threadIdx.x;
    const int bm   = blockIdx.y * 128;
    const int bn   = blockIdx.x * 128;
    const int warp = tid >> 5, lane = tid & 31;
    const int wm   = (warp & 3) * 32;
    const int wn   = (warp >> 2) * 64;
    const int g    = lane >> 2;           // row-in-8 group
    const int t    = lane & 3;            // k phase
    const int NC   = K >> 5;              // K chunks of 32
    const int KW   = K >> 1;              // uint32 per operand row

    const uint32_t sb = smem_u32(sm);
    const int lrow = tid >> 2;            // loader row 0..63 (+64)
    const int ltb  = tid & 3;             // 16B block within 64B row-chunk

    float acc[2][8][4];
    #pragma unroll
    for (int mt = 0; mt < 2; mt++)
        #pragma unroll
        for (int nt = 0; nt < 8; nt++)
            #pragma unroll
            for (int i = 0; i < 4; i++) acc[mt][nt][i] = 0.0f;

    const uint32_t* Ap = A  + (size_t)bm * KW;
    const uint32_t* Bp = Bw + (size_t)bn * KW;

    auto load_stage = [&](int stage, int c) {
        const uint32_t ab = sb + stage * STAGE_B;
        const uint32_t bb = ab + ATILE_B;
        #pragma unroll
        for (int p = 0; p < 2; p++) {
            const int row = lrow + p * 64;
            cp_async16(ab + (uint32_t)(row * 64 + ltb * 16),
                       Ap + (size_t)row * KW + c * 16 + ltb * 4);
            cp_async16(bb + (uint32_t)(row * 64 + ltb * 16),
                       Bp + (size_t)row * KW + c * 16 + ltb * 4);
        }
    };

    load_stage(0, 0);
    asm volatile("cp.async.commit_group;" ::: "memory");
    load_stage(1, 1);
    asm volatile("cp.async.commit_group;" ::: "memory");

    int buf = 0;
    for (int c = 0; c < NC; c++) {
        asm volatile("cp.async.wait_group 1;" ::: "memory");
        __syncthreads();

        if (c + 2 < NC) load_stage((buf + 2) % NSTG, c + 2);
        asm volatile("cp.async.commit_group;" ::: "memory");

        const uint32_t* sA = sm + buf * (STAGE_B / 4);
        const uint32_t* sB = sA + (ATILE_B / 4);

        // A fragments: one LDS.128 per row-half per mt covers the whole K32
        uint4 af[2][2];
        #pragma unroll
        for (int mt = 0; mt < 2; mt++) {
            const uint32_t* pa = sA + (wm + mt * 16 + g) * 16 + t * 4;
            af[mt][0] = *reinterpret_cast<const uint4*>(pa);
            af[mt][1] = *reinterpret_cast<const uint4*>(pa + 8 * 16);
        }
        // B in two halves of 4 nt to bound register pressure
        #pragma unroll
        for (int nh = 0; nh < 2; nh++) {
            uint4 bf[4];
            #pragma unroll
            for (int j = 0; j < 4; j++)
                bf[j] = *reinterpret_cast<const uint4*>(
                    sB + (wn + nh * 32 + j * 8 + g) * 16 + t * 4);
            #pragma unroll
            for (int mt = 0; mt < 2; mt++)
                #pragma unroll
                for (int j = 0; j < 4; j++) {
                    float* a = acc[mt][nh * 4 + j];
                    // k16 step 0: regs .x (k 0-7 part) / .y (k 8-15 part)
                    mma_f16(a, af[mt][0].x, af[mt][1].x, af[mt][0].y, af[mt][1].y,
                            bf[j].x, bf[j].y);
                    // k16 step 1: regs .z / .w (k 16-31)
                    mma_f16(a, af[mt][0].z, af[mt][1].z, af[mt][0].w, af[mt][1].w,
                            bf[j].z, bf[j].w);
                }
        }

        buf = (buf + 1) % NSTG;
    }

    // epilogue
    float*    Cf = (float*)Cout;
    uint32_t* Ch = (uint32_t*)Cout;
    #pragma unroll
    for (int mt = 0; mt < 2; mt++) {
        const int r0 = bm + wm + mt * 16 + g;
        #pragma unroll
        for (int nt = 0; nt < 8; nt++) {
            const int cc = bn + wn + nt * 8 + 2 * t;
            const float2 bv = *reinterpret_cast<const float2*>(bias + cc);
            float v00 = acc[mt][nt][0] + bv.x;
            float v01 = acc[mt][nt][1] + bv.y;
            float v10 = acc[mt][nt][2] + bv.x;
            float v11 = acc[mt][nt][3] + bv.y;
            if (MODE == 1) {
                v00 = fmaxf(v00, 0.0f); v01 = fmaxf(v01, 0.0f);
                v10 = fmaxf(v10, 0.0f); v11 = fmaxf(v11, 0.0f);
                const int u = hperm_u32(cc & 31) + (cc >> 5) * 16;
                Ch[(size_t)r0 * (N >> 1) + u]       = h2u(v00, v01);
                Ch[(size_t)(r0 + 8) * (N >> 1) + u] = h2u(v10, v11);
            } else {
                *reinterpret_cast<float2*>(Cf + (size_t)r0 * N + cc)
                    = make_float2(v00, v01);
                *reinterpret_cast<float2*>(Cf + (size_t)(r0 + 8) * N + cc)
                    = make_float2(v10, v11);
            }
        }
    }
}

// ---------------- elementwise kernels --------------------------------------
// fp32 -> fp16, k-permuted. Coalesced float4 reads; 2 scattered 4B writes
// per thread (within one 64B block run -> L2-coalesced).
__global__ void cvt_h_kernel(const float4* __restrict__ in,
                             uint32_t* __restrict__ out, int n4) {
    const int f = blockIdx.x * 256 + threadIdx.x;
    if (f >= n4) return;
    const float4 v = in[f];
    const int k0  = (f * 4) & 31;
    const int blk = f >> 3;
    out[blk * 16 + hperm_u32(k0)]     = h2u(v.x, v.y);
    out[blk * 16 + hperm_u32(k0 + 2)] = h2u(v.z, v.w);
}

__global__ void gru_kernel(const float4* __restrict__ hin,
                           float4* __restrict__ hout,
                           uint32_t* __restrict__ hc) {
    const int idx = blockIdx.x * 256 + threadIdx.x;      // over B*H/4
    const int b = idx >> 9;                              // H/4 = 512
    const int i = idx & 511;
    const float4* gi = reinterpret_cast<const float4*>(g_gi) + (size_t)b * (3 * H_DIM / 4);
    const float4* gh = reinterpret_cast<const float4*>(g_gh) + (size_t)b * (3 * H_DIM / 4);
    const float4 ir = gi[i], iz = gi[512 + i], inn = gi[1024 + i];
    const float4 hr = gh[i], hz = gh[512 + i], hn  = gh[1024 + i];
    const float4 h0 = hin[idx];
    float4 o;
    {
        float r = 1.0f / (1.0f + expf(-(ir.x + hr.x)));
        float z = 1.0f / (1.0f + expf(-(iz.x + hz.x)));
        float n = tanhf(inn.x + r * hn.x);
        o.x = (1.0f - z) * n + z * h0.x;
    }
    {
        float r = 1.0f / (1.0f + expf(-(ir.y + hr.y)));
        float z = 1.0f / (1.0f + expf(-(iz.y + hz.y)));
        float n = tanhf(inn.y + r * hn.y);
        o.y = (1.0f - z) * n + z * h0.y;
    }
    {
        float r = 1.0f / (1.0f + expf(-(ir.z + hr.z)));
        float z = 1.0f / (1.0f + expf(-(iz.z + hz.z)));
        float n = tanhf(inn.z + r * hn.z);
        o.z = (1.0f - z) * n + z * h0.z;
    }
    {
        float r = 1.0f / (1.0f + expf(-(ir.w + hr.w)));
        float z = 1.0f / (1.0f + expf(-(iz.w + hz.w)));
        float n = tanhf(inn.w + r * hn.w);
        o.w = (1.0f - z) * n + z * h0.w;
    }
    hout[idx] = o;
    // fp16 permuted hidden for fc2 (blocks never straddle rows: H % 32 == 0)
    const int e0  = idx * 4;
    const int kk  = e0 & 31;
    const int blk = e0 >> 5;
    hc[blk * 16 + hperm_u32(kk)]     = h2u(o.x, o.y);
    hc[blk * 16 + hperm_u32(kk + 2)] = h2u(o.z, o.w);
}

__global__ void decode_kernel(float* __restrict__ out) {
    __shared__ float s[A2_DIM];
    const int b = blockIdx.x;
    const float* qr = g_q + (size_t)b * A2_DIM;
    for (int i = threadIdx.x; i < A2_DIM; i += 256) s[i] = qr[i];
    __syncthreads();
    const int t = threadIdx.x;
    if (t < A_DIM) {
        float m = -3.402823466e38f;
        #pragma unroll 8
        for (int k = 0; k < A_DIM; k++) m = fmaxf(m, s[t + k]);
        out[(size_t)(2 * b) * A_DIM + t] = m;
    } else if (t < 2 * A_DIM) {
        const int j = t - A_DIM;
        float m = -3.402823466e38f;
        #pragma unroll 8
        for (int k = 0; k < A_DIM; k++)
            m = fmaxf(m, s[(j + A_DIM * k + (A2_DIM - 1)) & (A2_DIM - 1)]);
        out[(size_t)(2 * b + 1) * A_DIM + j] = m;
    }
}

// ---------------- launch ----------------------------------------------------
extern "C" void kernel_launch(void* const* d_in, const int* in_sizes, int n_in,
                              void* d_out, int out_size) {
    const float* inputs = (const float*)d_in[0];
    const float* hidden = (const float*)d_in[1];
    const float* W1  = (const float*)d_in[2];
    const float* b1  = (const float*)d_in[3];
    const float* Wih = (const float*)d_in[4];
    const float* Whh = (const float*)d_in[5];
    const float* bih = (const float*)d_in[6];
    const float* bhh = (const float*)d_in[7];
    const float* W2  = (const float*)d_in[8];
    const float* b2  = (const float*)d_in[9];
    float* out = (float*)d_out;
    float* hout = out + (size_t)2 * B_DIM * A_DIM;   // h region of output

    void *pinc, *phinc, *pW1c, *pWihc, *pWhhc, *pW2c, *px, *pgi, *pgh, *phc, *pq;
    cudaGetSymbolAddress(&pinc,  g_inc);
    cudaGetSymbolAddress(&phinc, g_hinc);
    cudaGetSymbolAddress(&pW1c,  g_W1c);
    cudaGetSymbolAddress(&pWihc, g_Wihc);
    cudaGetSymbolAddress(&pWhhc, g_Whhc);
    cudaGetSymbolAddress(&pW2c,  g_W2c);
    cudaGetSymbolAddress(&px,    g_x);
    cudaGetSymbolAddress(&pgi,   g_gi);
    cudaGetSymbolAddress(&pgh,   g_gh);
    cudaGetSymbolAddress(&phc,   g_hc);
    cudaGetSymbolAddress(&pq,    g_q);

    cudaFuncSetAttribute(gemm_f16k<0>, cudaFuncAttributeMaxDynamicSharedMemorySize, SMEM_BYTES);
    cudaFuncSetAttribute(gemm_f16k<1>, cudaFuncAttributeMaxDynamicSharedMemorySize, SMEM_BYTES);

    // fp32 -> fp16 (RN) + k-permute of raw GEMM operands
    auto cvt = [](const void* s, void* d, size_t n) {
        cvt_h_kernel<<<(unsigned)((n / 4 + 255) / 256), 256>>>(
            (const float4*)s, (uint32_t*)d, (int)(n / 4));
    };
    cvt(inputs, pinc,  (size_t)B_DIM * IN_DIM);
    cvt(hidden, phinc, (size_t)B_DIM * H_DIM);
    cvt(W1,  pW1c,  (size_t)H_DIM * IN_DIM);
    cvt(Wih, pWihc, (size_t)3 * H_DIM * H_DIM);
    cvt(Whh, pWhhc, (size_t)3 * H_DIM * H_DIM);
    cvt(W2,  pW2c,  (size_t)A2_DIM * H_DIM);

    const dim3 blk(256);

    // fc1 + relu (+fp16 perm): x = relu(inputs @ W1^T + b1)
    gemm_f16k<1><<<dim3(H_DIM / 128, B_DIM / 128), blk, SMEM_BYTES>>>(
        (const uint32_t*)pinc, (const uint32_t*)pW1c, b1, px, IN_DIM, H_DIM);

    // gi = x @ Wih^T + bih ; gh = h_in @ Whh^T + bhh
    gemm_f16k<0><<<dim3(3 * H_DIM / 128, B_DIM / 128), blk, SMEM_BYTES>>>(
        (const uint32_t*)px, (const uint32_t*)pWihc, bih, pgi, H_DIM, 3 * H_DIM);
    gemm_f16k<0><<<dim3(3 * H_DIM / 128, B_DIM / 128), blk, SMEM_BYTES>>>(
        (const uint32_t*)phinc, (const uint32_t*)pWhhc, bhh, pgh, H_DIM, 3 * H_DIM);

    // GRU elementwise -> exact h into d_out, fp16 permuted h into scratch
    gru_kernel<<<(B_DIM * H_DIM / 4) / 256, 256>>>(
        (const float4*)hidden, (float4*)hout, (uint32_t*)phc);

    // fc2: q = h @ W2^T + b2
    gemm_f16k<0><<<dim3(A2_DIM / 128, B_DIM / 128), blk, SMEM_BYTES>>>(
        (const uint32_t*)phc, (const uint32_t*)pW2c, b2, pq, H_DIM, A2_DIM);

    // decode -> d_out[0 .. 2B*A)
    decode_kernel<<<B_DIM, 256>>>(out);
}